// round 6
// baseline (speedup 1.0000x reference)
#include <cuda_runtime.h>
#include <math.h>

#define N_TOT  8192
#define NF     8
#define HID    64
#define TILE   16
#define NTHR   256
#define NBLK   (N_TOT / TILE)   // 512
#define HP2    (2 * TILE + 2)   // 34 floats: dup (h,h) pairs + pad

typedef unsigned long long ull;

__device__ __forceinline__ float sigm(float x) {
    return 1.0f / (1.0f + __expf(-x));
}

// Accurate tanh (only where it feeds an output directly).
__device__ __forceinline__ float tanh_acc(float x) {
    float ax = fabsf(x);
    if (ax < 0.0625f) {
        float x2 = x * x;
        return x * (1.0f + x2 * (-0.33333333f + x2 * 0.13333334f));
    }
    float e = __expf(-2.0f * ax);
    float r = (1.0f - e) / (1.0f + e);
    return (x < 0.0f) ? -r : r;
}

// HW tanh approximation (MUFU.TANH) for hidden layers.
__device__ __forceinline__ float tanha(float x) {
    float r;
    asm("tanh.approx.f32 %0, %1;" : "=f"(r) : "f"(x));
    return r;
}

// Packed dual-lane FMA / ADD (sm_103a f32x2; ptxas never emits from C++).
__device__ __forceinline__ ull fma2(ull a, ull b, ull c) {
    ull d;
    asm("fma.rn.f32x2 %0, %1, %2, %3;" : "=l"(d) : "l"(a), "l"(b), "l"(c));
    return d;
}
__device__ __forceinline__ ull addf2(ull a, ull b) {
    ull d;
    asm("add.rn.f32x2 %0, %1, %2;" : "=l"(d) : "l"(a), "l"(b));
    return d;
}
__device__ __forceinline__ float2 unpack2(ull v) {
    float2 r;
    asm("mov.b64 {%0, %1}, %2;" : "=f"(r.x), "=f"(r.y) : "l"(v));
    return r;
}

// ---------------------------------------------------------------------------
// Fused kernel: dual MLP (8->64->64->1) + quadrature + MIMICS epilogue.
// 512 blocks x 256 threads, 16 samples/block, K-SPLIT warp specialization:
//   threads t<128 (khalf 0) accumulate k in [0,K/2), threads t>=128 (khalf 1)
//   accumulate k in [K/2,K); partials meet in smem, combined with add.rn.f32x2.
// Per-thread microtile unchanged from the 16.9us kernel: 2 samples x 4 cols
// x 2 MLPs = 8 packed FFMA2 chains -> ptxas pipelines the weight LDGs.
// Same total L1 traffic as before, 2x the warps.
// Epilogue scalars + theta prefetched at kernel start (hide ~600cyc tail LDG).
// 128x32 orientation quadrature collapsed analytically to 3 theta moments
// (exact: uniform 32-pt phi-sum of cos^k, k<=4, equals continuous mean).
// ---------------------------------------------------------------------------
__global__ __launch_bounds__(NTHR, 3)
void pinn_kernel(const float* __restrict__ X,
                 const float* __restrict__ theta,
                 const float* __restrict__ Wp1, const float* __restrict__ bp1,
                 const float* __restrict__ Wp2, const float* __restrict__ bp2,
                 const float* __restrict__ Wp3, const float* __restrict__ bp3,
                 const float* __restrict__ Wc1, const float* __restrict__ bc1,
                 const float* __restrict__ Wc2, const float* __restrict__ bc2,
                 const float* __restrict__ Wc3, const float* __restrict__ bc3,
                 const float* __restrict__ nb_raw, const float* __restrict__ nl_raw,
                 const float* __restrict__ so_raw, const float* __restrict__ mg_raw,
                 const float* __restrict__ s_raw,
                 float* __restrict__ out) {
    __shared__ float XT2[NF][HP2];                  // duplicated (x,x)
    __shared__ float Hp[HID][HP2], Hc[HID][HP2];    // H1, then reused as H2
    __shared__ ulonglong2 Red[4][128];              // khalf1 partial sums
    __shared__ float qs[4][128];
    __shared__ float qsum[4];
    __shared__ float Ys[2][TILE];

    const int t = threadIdx.x;
    const int t127 = t & 127;
    const int kh = t >> 7;          // k-half this thread owns
    const int base = blockIdx.x * TILE;
    const float PI = 3.14159265358979f;

    // ---- prefetch epilogue scalars + theta EARLY (consumed at the end) ----
    float pf_nb = 0.f, pf_nl = 0.f, pf_mg = 0.f, pf_s = 0.f, pf_th = 0.f;
    if (t < TILE) {
        pf_nb = nb_raw[0]; pf_nl = nl_raw[0];
        pf_mg = mg_raw[0]; pf_s  = s_raw[0];
        pf_th = theta[base + t];
    }

    // ---- stage: quadrature points + X duplicated (t<128) ----
    if (t < 128) {
        float sig_o = (10.0f + 70.0f * sigm(so_raw[0])) * (PI / 180.0f);
        float th  = (float)t * (PI * 0.5f / 127.0f);   // linspace(0, pi/2, 128)
        float d   = th - PI * 0.25f;
        float pdf = expf(-d * d / (2.0f * sig_o * sig_o)) * sinf(th);
        float c = cosf(th), s = sinf(th);
        float c2 = c * c, s2 = s * s;
        qs[0][t] = pdf;
        qs[1][t] = pdf * c2 * c2;
        qs[2][t] = pdf * c2 * s2;
        qs[3][t] = pdf * s2 * s2;

        int r = t >> 3, k = t & 7;                     // 16*8 = 128 values
        float x = X[base * NF + t];
        *(float2*)&XT2[k][2 * r] = make_float2(x, x);
    }
    __syncthreads();

    // lane geometry (within each khalf): 16 colgroups x 8 sample-pairs
    const int c0 = (t127 & 15) * 4;        // 4 hidden cols owned
    const int s0 = (t127 >> 4) * 2;        // first of 2 samples owned

    // packed accumulators: [sample][colpair] for MLP p and c
    ull ap00, ap01, ap10, ap11, ac00, ac01, ac10, ac11;

    // ================= layer 1 (both MLPs): K = 8, split 4/4 ==============
    {
        if (kh == 0) {
            ulonglong2 bp = __ldg((const ulonglong2*)(bp1 + c0));
            ulonglong2 bc = __ldg((const ulonglong2*)(bc1 + c0));
            ap00 = bp.x; ap01 = bp.y; ap10 = bp.x; ap11 = bp.y;
            ac00 = bc.x; ac01 = bc.y; ac10 = bc.x; ac11 = bc.y;
        } else {
            ap00 = ap01 = ap10 = ap11 = 0ull;
            ac00 = ac01 = ac10 = ac11 = 0ull;
        }
        const int k0 = kh * 4;
        #pragma unroll
        for (int k = k0; k < k0 + 4; k++) {
            ull x0 = *(const ull*)&XT2[k][2 * s0];
            ull x1 = *(const ull*)&XT2[k][2 * s0 + 2];
            ulonglong2 wp = __ldg((const ulonglong2*)(Wp1 + k * HID + c0));
            ulonglong2 wc = __ldg((const ulonglong2*)(Wc1 + k * HID + c0));
            ap00 = fma2(x0, wp.x, ap00); ap01 = fma2(x0, wp.y, ap01);
            ap10 = fma2(x1, wp.x, ap10); ap11 = fma2(x1, wp.y, ap11);
            ac00 = fma2(x0, wc.x, ac00); ac01 = fma2(x0, wc.y, ac01);
            ac10 = fma2(x1, wc.x, ac10); ac11 = fma2(x1, wc.y, ac11);
        }
        if (kh == 1) {
            ulonglong2 v;
            v.x = ap00; v.y = ap01; Red[0][t127] = v;
            v.x = ap10; v.y = ap11; Red[1][t127] = v;
            v.x = ac00; v.y = ac01; Red[2][t127] = v;
            v.x = ac10; v.y = ac11; Red[3][t127] = v;
        }
    }
    __syncthreads();
    if (kh == 0) {
        ulonglong2 v;
        v = Red[0][t127]; ap00 = addf2(ap00, v.x); ap01 = addf2(ap01, v.y);
        v = Red[1][t127]; ap10 = addf2(ap10, v.x); ap11 = addf2(ap11, v.y);
        v = Red[2][t127]; ac00 = addf2(ac00, v.x); ac01 = addf2(ac01, v.y);
        v = Red[3][t127]; ac10 = addf2(ac10, v.x); ac11 = addf2(ac11, v.y);
        float2 u; float h;
        u = unpack2(ap00);
        h = tanha(u.x); *(float2*)&Hp[c0 + 0][2 * s0] = make_float2(h, h);
        h = tanha(u.y); *(float2*)&Hp[c0 + 1][2 * s0] = make_float2(h, h);
        u = unpack2(ap01);
        h = tanha(u.x); *(float2*)&Hp[c0 + 2][2 * s0] = make_float2(h, h);
        h = tanha(u.y); *(float2*)&Hp[c0 + 3][2 * s0] = make_float2(h, h);
        u = unpack2(ap10);
        h = tanha(u.x); *(float2*)&Hp[c0 + 0][2 * s0 + 2] = make_float2(h, h);
        h = tanha(u.y); *(float2*)&Hp[c0 + 1][2 * s0 + 2] = make_float2(h, h);
        u = unpack2(ap11);
        h = tanha(u.x); *(float2*)&Hp[c0 + 2][2 * s0 + 2] = make_float2(h, h);
        h = tanha(u.y); *(float2*)&Hp[c0 + 3][2 * s0 + 2] = make_float2(h, h);
        u = unpack2(ac00);
        h = tanha(u.x); *(float2*)&Hc[c0 + 0][2 * s0] = make_float2(h, h);
        h = tanha(u.y); *(float2*)&Hc[c0 + 1][2 * s0] = make_float2(h, h);
        u = unpack2(ac01);
        h = tanha(u.x); *(float2*)&Hc[c0 + 2][2 * s0] = make_float2(h, h);
        h = tanha(u.y); *(float2*)&Hc[c0 + 3][2 * s0] = make_float2(h, h);
        u = unpack2(ac10);
        h = tanha(u.x); *(float2*)&Hc[c0 + 0][2 * s0 + 2] = make_float2(h, h);
        h = tanha(u.y); *(float2*)&Hc[c0 + 1][2 * s0 + 2] = make_float2(h, h);
        u = unpack2(ac11);
        h = tanha(u.x); *(float2*)&Hc[c0 + 2][2 * s0 + 2] = make_float2(h, h);
        h = tanha(u.y); *(float2*)&Hc[c0 + 3][2 * s0 + 2] = make_float2(h, h);
    }
    __syncthreads();

    // ================= layer 2 (both MLPs): K = 64, split 32/32 ===========
    {
        if (kh == 0) {
            ulonglong2 bp = __ldg((const ulonglong2*)(bp2 + c0));
            ulonglong2 bc = __ldg((const ulonglong2*)(bc2 + c0));
            ap00 = bp.x; ap01 = bp.y; ap10 = bp.x; ap11 = bp.y;
            ac00 = bc.x; ac01 = bc.y; ac10 = bc.x; ac11 = bc.y;
        } else {
            ap00 = ap01 = ap10 = ap11 = 0ull;
            ac00 = ac01 = ac10 = ac11 = 0ull;
        }
        const int k0 = kh * 32;
        #pragma unroll 4
        for (int k = k0; k < k0 + 32; k++) {
            ull hp0 = *(const ull*)&Hp[k][2 * s0];
            ull hp1 = *(const ull*)&Hp[k][2 * s0 + 2];
            ull hc0 = *(const ull*)&Hc[k][2 * s0];
            ull hc1 = *(const ull*)&Hc[k][2 * s0 + 2];
            ulonglong2 wp = __ldg((const ulonglong2*)(Wp2 + k * HID + c0));
            ulonglong2 wc = __ldg((const ulonglong2*)(Wc2 + k * HID + c0));
            ap00 = fma2(hp0, wp.x, ap00); ap01 = fma2(hp0, wp.y, ap01);
            ap10 = fma2(hp1, wp.x, ap10); ap11 = fma2(hp1, wp.y, ap11);
            ac00 = fma2(hc0, wc.x, ac00); ac01 = fma2(hc0, wc.y, ac01);
            ac10 = fma2(hc1, wc.x, ac10); ac11 = fma2(hc1, wc.y, ac11);
        }
        if (kh == 1) {
            ulonglong2 v;
            v.x = ap00; v.y = ap01; Red[0][t127] = v;
            v.x = ap10; v.y = ap11; Red[1][t127] = v;
            v.x = ac00; v.y = ac01; Red[2][t127] = v;
            v.x = ac10; v.y = ac11; Red[3][t127] = v;
        }
    }
    __syncthreads();   // khalf1 partials visible; all H1 reads complete
    if (kh == 0) {
        ulonglong2 v;
        v = Red[0][t127]; ap00 = addf2(ap00, v.x); ap01 = addf2(ap01, v.y);
        v = Red[1][t127]; ap10 = addf2(ap10, v.x); ap11 = addf2(ap11, v.y);
        v = Red[2][t127]; ac00 = addf2(ac00, v.x); ac01 = addf2(ac01, v.y);
        v = Red[3][t127]; ac10 = addf2(ac10, v.x); ac11 = addf2(ac11, v.y);
        float2 u; float h;
        u = unpack2(ap00);
        h = tanha(u.x); *(float2*)&Hp[c0 + 0][2 * s0] = make_float2(h, h);
        h = tanha(u.y); *(float2*)&Hp[c0 + 1][2 * s0] = make_float2(h, h);
        u = unpack2(ap01);
        h = tanha(u.x); *(float2*)&Hp[c0 + 2][2 * s0] = make_float2(h, h);
        h = tanha(u.y); *(float2*)&Hp[c0 + 3][2 * s0] = make_float2(h, h);
        u = unpack2(ap10);
        h = tanha(u.x); *(float2*)&Hp[c0 + 0][2 * s0 + 2] = make_float2(h, h);
        h = tanha(u.y); *(float2*)&Hp[c0 + 1][2 * s0 + 2] = make_float2(h, h);
        u = unpack2(ap11);
        h = tanha(u.x); *(float2*)&Hp[c0 + 2][2 * s0 + 2] = make_float2(h, h);
        h = tanha(u.y); *(float2*)&Hp[c0 + 3][2 * s0 + 2] = make_float2(h, h);
        u = unpack2(ac00);
        h = tanha(u.x); *(float2*)&Hc[c0 + 0][2 * s0] = make_float2(h, h);
        h = tanha(u.y); *(float2*)&Hc[c0 + 1][2 * s0] = make_float2(h, h);
        u = unpack2(ac01);
        h = tanha(u.x); *(float2*)&Hc[c0 + 2][2 * s0] = make_float2(h, h);
        h = tanha(u.y); *(float2*)&Hc[c0 + 3][2 * s0] = make_float2(h, h);
        u = unpack2(ac10);
        h = tanha(u.x); *(float2*)&Hc[c0 + 0][2 * s0 + 2] = make_float2(h, h);
        h = tanha(u.y); *(float2*)&Hc[c0 + 1][2 * s0 + 2] = make_float2(h, h);
        u = unpack2(ac11);
        h = tanha(u.x); *(float2*)&Hc[c0 + 2][2 * s0 + 2] = make_float2(h, h);
        h = tanha(u.y); *(float2*)&Hc[c0 + 3][2 * s0 + 2] = make_float2(h, h);
    }
    __syncthreads();

    // ---- parallel: warps 0-1 reduce quadrature; warp 2 does layer 3 ----
    {
        int w = t >> 5, lane = t & 31;
        if (w < 2) {
            #pragma unroll
            for (int a = 2 * w; a < 2 * w + 2; a++) {
                float v = qs[a][lane] + qs[a][lane + 32]
                        + qs[a][lane + 64] + qs[a][lane + 96];
                v += __shfl_xor_sync(0xFFFFFFFF, v, 16);
                v += __shfl_xor_sync(0xFFFFFFFF, v, 8);
                v += __shfl_xor_sync(0xFFFFFFFF, v, 4);
                v += __shfl_xor_sync(0xFFFFFFFF, v, 2);
                v += __shfl_xor_sync(0xFFFFFFFF, v, 1);
                if (lane == 0) qsum[a] = v;
            }
        } else if (w == 2) {
            int idx = t - 64;                  // 0..31
            int mlp = idx >> 4, rr = idx & 15; // 2 MLPs x 16 samples
            const float* W3 = mlp ? Wc3 : Wp3;
            const float* H2 = mlp ? &Hc[0][0] : &Hp[0][0];
            float v0 = __ldg(mlp ? bc3 : bp3);
            float v1 = 0.f, v2 = 0.f, v3 = 0.f;
            #pragma unroll 4
            for (int k = 0; k < HID; k += 4) {
                v0 = fmaf(H2[(k + 0) * HP2 + 2 * rr], __ldg(W3 + k + 0), v0);
                v1 = fmaf(H2[(k + 1) * HP2 + 2 * rr], __ldg(W3 + k + 1), v1);
                v2 = fmaf(H2[(k + 2) * HP2 + 2 * rr], __ldg(W3 + k + 2), v2);
                v3 = fmaf(H2[(k + 3) * HP2 + 2 * rr], __ldg(W3 + k + 3), v3);
            }
            Ys[mlp][rr] = (v0 + v1) + (v2 + v3);
        }
    }
    __syncthreads();

    // ---- epilogue: MIMICS physics, analytically reduced quadrature ----
    if (t < TILE) {
        int s = base + t;

        float inv = 1.0f / qsum[0];
        float S1 = qsum[1] * inv, S2 = qsum[2] * inv, S3 = qsum[3] * inv;

        float Nb = exp10f(2.0f + 3.0f * sigm(pf_nb));
        float Nl = exp10f(3.0f + 3.0f * sigm(pf_nl));
        float dens = Nb * 1e-4f + Nl * 1e-6f;

        float mg   = 0.05f + 0.75f * sigm(pf_mg);
        float epsv = 1.5f + 20.0f * mg;
        float Kv   = (epsv - 1.0f) / (epsv + 2.0f);
        float Kv2  = Kv * Kv;

        float sm = 0.01f * (0.5f + 5.5f * sigm(pf_s));
        float kw = 2.0f * PI * (5.405e9f / 2.998e8f);
        float tt = 2.0f * kw * sm;
        float c_r = tt * tt;

        float m_v   = 0.93f * sigm(Ys[0][t]);
        float delta = 0.05f * tanh_acc(Ys[1][t]);   // direct output: exact tanh
        float eps_g = 3.0f + 25.0f * m_v + 10.0f * m_v * m_v;

        float ti = pf_th * (PI / 180.0f);
        float ct = cosf(ti), st = sinf(ti);
        float ct2 = ct * ct, st2 = st * st;

        float crown_vv = Kv2 * (ct2 * ct2 * S1 + 3.0f * ct2 * st2 * S2
                                + 0.375f * st2 * st2 * S3);
        float crown_vh = Kv2 * (0.5f * ct2 * S2 + 0.125f * st2 * S3);

        float root  = sqrtf(eps_g - st2);
        float r_v   = (eps_g * ct - root) / (eps_g * ct + root);
        float gamma = r_v * r_v;
        float rough = expf(-c_r * ct2);
        float ground = gamma * rough * ct2;

        float svv = dens * crown_vv + ground;
        float svh = dens * crown_vh + 0.05f * ground;

        out[0 * N_TOT + s] = m_v;
        out[1 * N_TOT + s] = delta;
        out[2 * N_TOT + s] = m_v + delta;
        out[3 * N_TOT + s] = 10.0f * log10f(svv + 1e-12f);
        out[4 * N_TOT + s] = 10.0f * log10f(svh + 1e-12f);
        out[5 * N_TOT + s] = eps_g;
    }
}

extern "C" void kernel_launch(void* const* d_in, const int* in_sizes, int n_in,
                              void* d_out, int out_size) {
    // inputs: 0 X, 1 theta_inc_deg, 2 vv_db_observed (unused),
    // 3 Wp1, 4 bp1, 5 Wp2, 6 bp2, 7 Wp3, 8 bp3,
    // 9 Wc1, 10 bc1, 11 Wc2, 12 bc2, 13 Wc3, 14 bc3,
    // 15 nb_raw, 16 nl_raw, 17 so_raw, 18 mg_raw, 19 s_raw
    (void)in_sizes; (void)n_in; (void)out_size;

    pinn_kernel<<<NBLK, NTHR>>>(
        (const float*)d_in[0], (const float*)d_in[1],
        (const float*)d_in[3], (const float*)d_in[4],
        (const float*)d_in[5], (const float*)d_in[6],
        (const float*)d_in[7], (const float*)d_in[8],
        (const float*)d_in[9], (const float*)d_in[10],
        (const float*)d_in[11], (const float*)d_in[12],
        (const float*)d_in[13], (const float*)d_in[14],
        (const float*)d_in[15], (const float*)d_in[16],
        (const float*)d_in[17], (const float*)d_in[18],
        (const float*)d_in[19],
        (float*)d_out);
}

// round 7
// speedup vs baseline: 1.6875x; 1.6875x over previous
#include <cuda_runtime.h>
#include <math.h>

#define N_TOT  8192
#define NF     8
#define HID    64
#define TILE   16
#define NTHR   128
#define NBLK   (N_TOT / TILE)   // 512
#define PIT    20               // smem row pitch in floats (80B: 16B-aligned rows)

typedef unsigned long long ull;

__device__ __forceinline__ float sigm(float x) {
    return 1.0f / (1.0f + __expf(-x));
}

// Accurate tanh (only where it feeds an output directly).
__device__ __forceinline__ float tanh_acc(float x) {
    float ax = fabsf(x);
    if (ax < 0.0625f) {
        float x2 = x * x;
        return x * (1.0f + x2 * (-0.33333333f + x2 * 0.13333334f));
    }
    float e = __expf(-2.0f * ax);
    float r = (1.0f - e) / (1.0f + e);
    return (x < 0.0f) ? -r : r;
}

// HW tanh approximation (MUFU.TANH) for hidden layers.
__device__ __forceinline__ float tanha(float x) {
    float r;
    asm("tanh.approx.f32 %0, %1;" : "=f"(r) : "f"(x));
    return r;
}

// Packed dual-lane FMA (sm_103a FFMA2; ptxas never emits from C++).
__device__ __forceinline__ ull fma2(ull a, ull b, ull c) {
    ull d;
    asm("fma.rn.f32x2 %0, %1, %2, %3;" : "=l"(d) : "l"(a), "l"(b), "l"(c));
    return d;
}
__device__ __forceinline__ float2 unpack2(ull v) {
    float2 r;
    asm("mov.b64 {%0, %1}, %2;" : "=f"(r.x), "=f"(r.y) : "l"(v));
    return r;
}
__device__ __forceinline__ ull dup2(float x) {
    ull d;
    asm("mov.b64 %0, {%1, %1};" : "=l"(d) : "f"(x));
    return d;
}

// ---------------------------------------------------------------------------
// Fused kernel: dual MLP (8->64->64->1) + quadrature + MIMICS epilogue.
// 512 blocks x 128 threads, 16 samples/block.
// SAMPLE-PACKED FFMA2: thread owns 1 column (c=t&63) and 8 samples (4 packed
// pairs, sg=t>>6) for BOTH MLPs = 8 FFMA2 chains (same ILP as the 16.9us
// kernel). Activations live in [col][sample] smem rows -> packed a-operands
// are natural float2s fetched by broadcast LDS.128 (1 wavefront each), and
// weights are warp-coalesced LDG.32 (1 wavefront) duplicated with 1 ALU mov.
// Hot-loop L1 wavefronts per 512 FMAs: ~6 (was ~16 with column packing).
// 128x32 orientation quadrature collapsed analytically to 3 theta moments
// (exact: uniform 32-pt phi-sum of cos^k, k<=4, equals continuous mean).
// ---------------------------------------------------------------------------
__global__ __launch_bounds__(NTHR)
void pinn_kernel(const float* __restrict__ X,
                 const float* __restrict__ theta,
                 const float* __restrict__ Wp1, const float* __restrict__ bp1,
                 const float* __restrict__ Wp2, const float* __restrict__ bp2,
                 const float* __restrict__ Wp3, const float* __restrict__ bp3,
                 const float* __restrict__ Wc1, const float* __restrict__ bc1,
                 const float* __restrict__ Wc2, const float* __restrict__ bc2,
                 const float* __restrict__ Wc3, const float* __restrict__ bc3,
                 const float* __restrict__ nb_raw, const float* __restrict__ nl_raw,
                 const float* __restrict__ so_raw, const float* __restrict__ mg_raw,
                 const float* __restrict__ s_raw,
                 float* __restrict__ out) {
    __shared__ float XT [NF ][PIT];                  // [feature][sample]
    __shared__ float H1p[HID][PIT], H1c[HID][PIT];   // [col][sample]
    __shared__ float H2p[HID][PIT], H2c[HID][PIT];
    __shared__ float qs[4][NTHR];
    __shared__ float qsum[4];
    __shared__ float Ys[2][TILE];

    const int t = threadIdx.x;
    const int base = blockIdx.x * TILE;
    const float PI = 3.14159265358979f;

    // ---- prefetch epilogue scalars + theta EARLY ----
    float pf_nb = 0.f, pf_nl = 0.f, pf_mg = 0.f, pf_s = 0.f, pf_th = 0.f;
    if (t < TILE) {
        pf_nb = nb_raw[0]; pf_nl = nl_raw[0];
        pf_mg = mg_raw[0]; pf_s  = s_raw[0];
        pf_th = theta[base + t];
    }

    // ---- stage: quadrature point per thread + X [feature][sample] ----
    {
        float sig_o = (10.0f + 70.0f * sigm(so_raw[0])) * (PI / 180.0f);
        float th  = (float)t * (PI * 0.5f / 127.0f);   // linspace(0, pi/2, 128)
        float d   = th - PI * 0.25f;
        float pdf = expf(-d * d / (2.0f * sig_o * sig_o)) * sinf(th);
        float c = cosf(th), s = sinf(th);
        float c2 = c * c, s2 = s * s;
        qs[0][t] = pdf;
        qs[1][t] = pdf * c2 * c2;
        qs[2][t] = pdf * c2 * s2;
        qs[3][t] = pdf * s2 * s2;

        int r = t >> 3, k = t & 7;                     // 16*8 = 128 values
        XT[k][r] = X[base * NF + t];
    }
    __syncthreads();

    // lane geometry: 1 column, 8 samples (4 packed pairs)
    const int c   = t & 63;          // hidden column owned
    const int sg8 = (t >> 6) * 8;    // first sample owned

    ull ap0, ap1, ap2, ap3, ac0, ac1, ac2, ac3;   // packed (s,s+1) accs

    // ================= layer 1 (both MLPs): K = 8 =================
    {
        ull bp = dup2(__ldg(bp1 + c));
        ull bc = dup2(__ldg(bc1 + c));
        ap0 = bp; ap1 = bp; ap2 = bp; ap3 = bp;
        ac0 = bc; ac1 = bc; ac2 = bc; ac3 = bc;
        #pragma unroll
        for (int k = 0; k < NF; k++) {
            ulonglong2 A0 = *(const ulonglong2*)&XT[k][sg8];       // pairs 0,1
            ulonglong2 A1 = *(const ulonglong2*)&XT[k][sg8 + 4];   // pairs 2,3
            ull wp = dup2(__ldg(Wp1 + k * HID + c));
            ull wc = dup2(__ldg(Wc1 + k * HID + c));
            ap0 = fma2(A0.x, wp, ap0); ap1 = fma2(A0.y, wp, ap1);
            ap2 = fma2(A1.x, wp, ap2); ap3 = fma2(A1.y, wp, ap3);
            ac0 = fma2(A0.x, wc, ac0); ac1 = fma2(A0.y, wc, ac1);
            ac2 = fma2(A1.x, wc, ac2); ac3 = fma2(A1.y, wc, ac3);
        }
        float2 u;
        u = unpack2(ap0); *(float2*)&H1p[c][sg8 + 0] = make_float2(tanha(u.x), tanha(u.y));
        u = unpack2(ap1); *(float2*)&H1p[c][sg8 + 2] = make_float2(tanha(u.x), tanha(u.y));
        u = unpack2(ap2); *(float2*)&H1p[c][sg8 + 4] = make_float2(tanha(u.x), tanha(u.y));
        u = unpack2(ap3); *(float2*)&H1p[c][sg8 + 6] = make_float2(tanha(u.x), tanha(u.y));
        u = unpack2(ac0); *(float2*)&H1c[c][sg8 + 0] = make_float2(tanha(u.x), tanha(u.y));
        u = unpack2(ac1); *(float2*)&H1c[c][sg8 + 2] = make_float2(tanha(u.x), tanha(u.y));
        u = unpack2(ac2); *(float2*)&H1c[c][sg8 + 4] = make_float2(tanha(u.x), tanha(u.y));
        u = unpack2(ac3); *(float2*)&H1c[c][sg8 + 6] = make_float2(tanha(u.x), tanha(u.y));
    }
    __syncthreads();

    // ================= layer 2 (both MLPs): K = 64 =================
    {
        ull bp = dup2(__ldg(bp2 + c));
        ull bc = dup2(__ldg(bc2 + c));
        ap0 = bp; ap1 = bp; ap2 = bp; ap3 = bp;
        ac0 = bc; ac1 = bc; ac2 = bc; ac3 = bc;
        #pragma unroll 8
        for (int k = 0; k < HID; k++) {
            ulonglong2 Ap0 = *(const ulonglong2*)&H1p[k][sg8];
            ulonglong2 Ap1 = *(const ulonglong2*)&H1p[k][sg8 + 4];
            ulonglong2 Ac0 = *(const ulonglong2*)&H1c[k][sg8];
            ulonglong2 Ac1 = *(const ulonglong2*)&H1c[k][sg8 + 4];
            ull wp = dup2(__ldg(Wp2 + k * HID + c));
            ull wc = dup2(__ldg(Wc2 + k * HID + c));
            ap0 = fma2(Ap0.x, wp, ap0); ap1 = fma2(Ap0.y, wp, ap1);
            ap2 = fma2(Ap1.x, wp, ap2); ap3 = fma2(Ap1.y, wp, ap3);
            ac0 = fma2(Ac0.x, wc, ac0); ac1 = fma2(Ac0.y, wc, ac1);
            ac2 = fma2(Ac1.x, wc, ac2); ac3 = fma2(Ac1.y, wc, ac3);
        }
        // H2 is a separate buffer: no hazard with pending H1 reads
        float2 u;
        u = unpack2(ap0); *(float2*)&H2p[c][sg8 + 0] = make_float2(tanha(u.x), tanha(u.y));
        u = unpack2(ap1); *(float2*)&H2p[c][sg8 + 2] = make_float2(tanha(u.x), tanha(u.y));
        u = unpack2(ap2); *(float2*)&H2p[c][sg8 + 4] = make_float2(tanha(u.x), tanha(u.y));
        u = unpack2(ap3); *(float2*)&H2p[c][sg8 + 6] = make_float2(tanha(u.x), tanha(u.y));
        u = unpack2(ac0); *(float2*)&H2c[c][sg8 + 0] = make_float2(tanha(u.x), tanha(u.y));
        u = unpack2(ac1); *(float2*)&H2c[c][sg8 + 2] = make_float2(tanha(u.x), tanha(u.y));
        u = unpack2(ac2); *(float2*)&H2c[c][sg8 + 4] = make_float2(tanha(u.x), tanha(u.y));
        u = unpack2(ac3); *(float2*)&H2c[c][sg8 + 6] = make_float2(tanha(u.x), tanha(u.y));
    }
    __syncthreads();

    // ---- parallel: warps 0-1 reduce quadrature; warp 2 does layer 3 ----
    {
        int w = t >> 5, lane = t & 31;
        if (w < 2) {
            #pragma unroll
            for (int a = 2 * w; a < 2 * w + 2; a++) {
                float v = qs[a][lane] + qs[a][lane + 32]
                        + qs[a][lane + 64] + qs[a][lane + 96];
                v += __shfl_xor_sync(0xFFFFFFFF, v, 16);
                v += __shfl_xor_sync(0xFFFFFFFF, v, 8);
                v += __shfl_xor_sync(0xFFFFFFFF, v, 4);
                v += __shfl_xor_sync(0xFFFFFFFF, v, 2);
                v += __shfl_xor_sync(0xFFFFFFFF, v, 1);
                if (lane == 0) qsum[a] = v;
            }
        } else if (w == 2) {
            int idx = t - 64;                  // 0..31
            int mlp = idx >> 4, rr = idx & 15; // 2 MLPs x 16 samples
            const float* W3 = mlp ? Wc3 : Wp3;
            const float* H2 = mlp ? &H2c[0][0] : &H2p[0][0];
            float v0 = __ldg(mlp ? bc3 : bp3);
            float v1 = 0.f, v2 = 0.f, v3 = 0.f;
            #pragma unroll 4
            for (int k = 0; k < HID; k += 4) {  // k = column index here
                v0 = fmaf(H2[(k + 0) * PIT + rr], __ldg(W3 + k + 0), v0);
                v1 = fmaf(H2[(k + 1) * PIT + rr], __ldg(W3 + k + 1), v1);
                v2 = fmaf(H2[(k + 2) * PIT + rr], __ldg(W3 + k + 2), v2);
                v3 = fmaf(H2[(k + 3) * PIT + rr], __ldg(W3 + k + 3), v3);
            }
            Ys[mlp][rr] = (v0 + v1) + (v2 + v3);
        }
    }
    __syncthreads();

    // ---- epilogue: MIMICS physics, analytically reduced quadrature ----
    if (t < TILE) {
        int s = base + t;

        float inv = 1.0f / qsum[0];
        float S1 = qsum[1] * inv, S2 = qsum[2] * inv, S3 = qsum[3] * inv;

        float Nb = exp10f(2.0f + 3.0f * sigm(pf_nb));
        float Nl = exp10f(3.0f + 3.0f * sigm(pf_nl));
        float dens = Nb * 1e-4f + Nl * 1e-6f;

        float mg   = 0.05f + 0.75f * sigm(pf_mg);
        float epsv = 1.5f + 20.0f * mg;
        float Kv   = (epsv - 1.0f) / (epsv + 2.0f);
        float Kv2  = Kv * Kv;

        float sm = 0.01f * (0.5f + 5.5f * sigm(pf_s));
        float kw = 2.0f * PI * (5.405e9f / 2.998e8f);
        float tt = 2.0f * kw * sm;
        float c_r = tt * tt;

        float m_v   = 0.93f * sigm(Ys[0][t]);
        float delta = 0.05f * tanh_acc(Ys[1][t]);   // direct output: exact tanh
        float eps_g = 3.0f + 25.0f * m_v + 10.0f * m_v * m_v;

        float ti = pf_th * (PI / 180.0f);
        float ct = cosf(ti), st = sinf(ti);
        float ct2 = ct * ct, st2 = st * st;

        float crown_vv = Kv2 * (ct2 * ct2 * S1 + 3.0f * ct2 * st2 * S2
                                + 0.375f * st2 * st2 * S3);
        float crown_vh = Kv2 * (0.5f * ct2 * S2 + 0.125f * st2 * S3);

        float root  = sqrtf(eps_g - st2);
        float r_v   = (eps_g * ct - root) / (eps_g * ct + root);
        float gamma = r_v * r_v;
        float rough = expf(-c_r * ct2);
        float ground = gamma * rough * ct2;

        float svv = dens * crown_vv + ground;
        float svh = dens * crown_vh + 0.05f * ground;

        out[0 * N_TOT + s] = m_v;
        out[1 * N_TOT + s] = delta;
        out[2 * N_TOT + s] = m_v + delta;
        out[3 * N_TOT + s] = 10.0f * log10f(svv + 1e-12f);
        out[4 * N_TOT + s] = 10.0f * log10f(svh + 1e-12f);
        out[5 * N_TOT + s] = eps_g;
    }
}

extern "C" void kernel_launch(void* const* d_in, const int* in_sizes, int n_in,
                              void* d_out, int out_size) {
    // inputs: 0 X, 1 theta_inc_deg, 2 vv_db_observed (unused),
    // 3 Wp1, 4 bp1, 5 Wp2, 6 bp2, 7 Wp3, 8 bp3,
    // 9 Wc1, 10 bc1, 11 Wc2, 12 bc2, 13 Wc3, 14 bc3,
    // 15 nb_raw, 16 nl_raw, 17 so_raw, 18 mg_raw, 19 s_raw
    (void)in_sizes; (void)n_in; (void)out_size;

    pinn_kernel<<<NBLK, NTHR>>>(
        (const float*)d_in[0], (const float*)d_in[1],
        (const float*)d_in[3], (const float*)d_in[4],
        (const float*)d_in[5], (const float*)d_in[6],
        (const float*)d_in[7], (const float*)d_in[8],
        (const float*)d_in[9], (const float*)d_in[10],
        (const float*)d_in[11], (const float*)d_in[12],
        (const float*)d_in[13], (const float*)d_in[14],
        (const float*)d_in[15], (const float*)d_in[16],
        (const float*)d_in[17], (const float*)d_in[18],
        (const float*)d_in[19],
        (float*)d_out);
}